// round 7
// baseline (speedup 1.0000x reference)
#include <cuda_runtime.h>
#include <cstdint>

typedef unsigned long long u64;
#define DEV static __device__ __forceinline__

static constexpr int L_ = 3;
static constexpr int NB = 128;    // 128 CTAs, 8 rows each
static constexpr int NT = 1024;   // 32 warps, 8 per SMSP

// ---------------- device globals ----------------
__device__ float g_P[2][1024 * 128];   // double-buffered Pj
__device__ float g_Wc[L_][128 * 128];  // ew2 @ nw1b
__device__ float g_cb[L_][128];        // eb2 @ nw1b
__device__ unsigned g_bar[4];          // monotonic barrier counters (replay-safe)

// ---------------- f32x2 helpers ----------------
DEV u64 pk(float lo, float hi) {
    u64 r; asm("mov.b64 %0,{%1,%2};" : "=l"(r) : "f"(lo), "f"(hi)); return r;
}
DEV void upk(u64 v, float& lo, float& hi) {
    asm("mov.b64 {%0,%1},%2;" : "=f"(lo), "=f"(hi) : "l"(v));
}
DEV u64 add2(u64 a, u64 b) {
    u64 r; asm("add.rn.f32x2 %0,%1,%2;" : "=l"(r) : "l"(a), "l"(b)); return r;
}
DEV u64 fma2(u64 a, u64 b, u64 c) {
    u64 r; asm("fma.rn.f32x2 %0,%1,%2,%3;" : "=l"(r) : "l"(a), "l"(b), "l"(c)); return r;
}
DEV u64 relu2(u64 v) {
    float lo, hi; upk(v, lo, hi);
    return pk(fmaxf(lo, 0.f), fmaxf(hi, 0.f));
}

// ---------------- cp.async helpers ----------------
DEV void cpa16(void* dst, const void* src) {
    unsigned d = (unsigned)__cvta_generic_to_shared(dst);
    asm volatile("cp.async.cg.shared.global [%0],[%1],16;" :: "r"(d), "l"(src) : "memory");
}
DEV void cpa_commit() { asm volatile("cp.async.commit_group;" ::: "memory"); }
DEV void cpa_wait0() { asm volatile("cp.async.wait_group 0;" ::: "memory"); }
DEV void cpa_wait1() { asm volatile("cp.async.wait_group 1;" ::: "memory"); }

// stage 64KB (16384 floats) with 1024 threads, one commit group
DEV void stage64(float* dst, const float* src, int tid) {
#pragma unroll
    for (int i = 0; i < 4; i++)
        cpa16(dst + (i * 1024 + tid) * 4, src + (i * 1024 + tid) * 4);
    cpa_commit();
}

// ---------------- grid barrier (monotonic counter; replay-safe) ----------------
DEV unsigned ld_acq(const unsigned* p) {
    unsigned v;
    asm volatile("ld.acquire.gpu.global.u32 %0,[%1];" : "=r"(v) : "l"(p) : "memory");
    return v;
}
DEV void grid_barrier(int bidx, int tid) {
    __syncthreads();
    if (tid == 0) {
        __threadfence();
        unsigned t = atomicAdd(&g_bar[bidx], 1u);
        unsigned target = (t / (unsigned)NB + 1u) * (unsigned)NB;
        while (ld_acq(&g_bar[bidx]) < target) { __nanosleep(64); }
        __threadfence();
    }
    __syncthreads();
}

// ---------------- GEMM: warp=(cg2,rg2,kq8), thread = 4 rows x 2 cols ----------------
// dup'd A: ATs[k*20 + 2r] = ATs[k*20+2r+1] = A[r][k]
DEV void gemm_t(const float* __restrict__ ATs, const float* __restrict__ Wsm,
                int lane, int cg, int rg, int kq, u64 acc[4]) {
    const float* ap = ATs + kq * 16 * 20 + rg * 8;
    const float* wp = Wsm + kq * 16 * 128 + cg * 64 + lane * 2;
#pragma unroll 8
    for (int k = 0; k < 16; k++) {
        ulonglong2 a01 = *(const ulonglong2*)(ap + k * 20);
        ulonglong2 a23 = *(const ulonglong2*)(ap + k * 20 + 4);
        u64 wv = *(const u64*)(wp + k * 128);
        acc[0] = fma2(a01.x, wv, acc[0]);
        acc[1] = fma2(a01.y, wv, acc[1]);
        acc[2] = fma2(a23.x, wv, acc[2]);
        acc[3] = fma2(a23.y, wv, acc[3]);
    }
}

DEV void store_part(float* sPart, const u64 acc[4], int lane, int cg, int rg, int kq) {
    float* o = sPart + kq * 1024 + rg * 512 + cg * 64 + lane * 2;
#pragma unroll
    for (int r = 0; r < 4; r++) *(u64*)(o + r * 128) = acc[r];
}

DEV float reduce8(const float* __restrict__ sPart, int idx) {
    float v = 0.f;
#pragma unroll
    for (int p = 0; p < 8; p++) v += sPart[p * 1024 + idx];
    return v;
}

// ---------------- agg half: warp=(ig4,jq8), thread = 2 i x 4 d, 16 j ----------------
DEV void agg_half(const float* __restrict__ Pjh, const float* __restrict__ adjh,
                  const u64 xi[2][2], u64 acc[2][2], int lane, int ig, int jq) {
    const float* pj = Pjh + jq * 16 * 128 + lane * 4;
    const float* ad = adjh + jq * 16 * 16 + ig * 4;
#pragma unroll 8
    for (int jj = 0; jj < 16; jj++) {
        ulonglong2 xj = *(const ulonglong2*)(pj + jj * 128);
        ulonglong2 aa = *(const ulonglong2*)(ad + jj * 16);   // (dup a_i0, dup a_i1)
        u64 t;
        t = relu2(add2(xi[0][0], xj.x)); acc[0][0] = fma2(t, aa.x, acc[0][0]);
        t = relu2(add2(xi[0][1], xj.y)); acc[0][1] = fma2(t, aa.x, acc[0][1]);
        t = relu2(add2(xi[1][0], xj.x)); acc[1][0] = fma2(t, aa.y, acc[1][0]);
        t = relu2(add2(xi[1][1], xj.y)); acc[1][1] = fma2(t, aa.y, acc[1][1]);
    }
}

// ---------------- smem layout (floats) ----------------
// b0 0 (16384) | b1 16384 (16384) | sPart 32768 (8192) | sATs 40960 (2560)
// sNTs 43520 (2560) | sPi 46080 (1024) | sPn 47104 (1024) | sAdj2 48128 (4096)
// s_rs 52224 (8) | sX 52232 (1024)
static constexpr int SMEM_FLOATS = 53256;   // 213024 B

__global__ void __launch_bounds__(NT, 1) k_main(
    float* __restrict__ x, const float* __restrict__ nf, const float* __restrict__ adj,
    const float* __restrict__ ew1, const float* __restrict__ eb1,
    const float* __restrict__ ew2, const float* __restrict__ eb2,
    const float* __restrict__ nw1, const float* __restrict__ nb1,
    const float* __restrict__ nw2, const float* __restrict__ nb2) {
    extern __shared__ float sm[];
    float* b0 = sm;
    float* b1 = sm + 16384;
    float* sPart = sm + 32768;
    float* sATs = sm + 40960;
    float* sNTs = sm + 43520;
    float* sPi = sm + 46080;
    float* sPn = sm + 47104;
    float* sAdj2 = sm + 48128;
    float* s_rs = sm + 52224;
    float* sX = sm + 52232;

    int tid = threadIdx.x, lane = tid & 31, w = tid >> 5;
    int rb = blockIdx.x;        // rows rb*8 .. rb*8+7
    int b = rb >> 5;            // batch
    int il0 = (rb & 31) * 8;    // local i base in batch
    int cg = w & 1, rg = (w >> 1) & 1, kq = w >> 2;   // gemm roles
    int ig = w & 3, jq = w >> 2;                      // agg roles
    int rr = tid >> 7, cc = tid & 127;                // reduce/epilogue roles

    // ================= setup =================
    sX[tid] = nf[rb * 1024 + tid];

    const float* adjb = adj + (size_t)(b * 256 + il0) * 256;
#pragma unroll
    for (int e = 0; e < 2; e++) {
        int idx = e * 1024 + tid;
        int r = idx >> 8, j = idx & 255;
        float v = adjb[r * 256 + j];
        sAdj2[j * 16 + 2 * r] = v;
        sAdj2[j * 16 + 2 * r + 1] = v;
    }
    if (w < 8) {
        float s = 0.f;
        const float* row = adjb + w * 256;
#pragma unroll
        for (int j = lane; j < 256; j += 32) s += row[j];
#pragma unroll
        for (int o = 16; o; o >>= 1) s += __shfl_xor_sync(~0u, s, o);
        if (!lane) s_rs[w] = s;
    }
    if (rb < 48) {   // Wc[l] = ew2[l] @ nw1b[l]
        int l = rb / 16, r8 = rb % 16;
        stage64(b0, nw1 + l * 32768 + 16384, tid);
        {
            float v = ew2[l * 16384 + (r8 * 8 + rr) * 128 + cc];
            sATs[cc * 20 + 2 * rr] = v;
            sATs[cc * 20 + 2 * rr + 1] = v;
        }
        cpa_wait0();
        __syncthreads();
        u64 acc[4] = {};
        gemm_t(sATs, b0, lane, cg, rg, kq, acc);
        store_part(sPart, acc, lane, cg, rg, kq);
        __syncthreads();
        g_Wc[l][(r8 * 8 + rr) * 128 + cc] = reduce8(sPart, tid);
    } else if (rb == 48) {
        if (tid < 384) {
            int l = tid >> 7, c = tid & 127;
            const float* e2 = eb2 + l * 128;
            const float* W = nw1 + l * 32768 + 16384 + c;
            float s = 0.f;
#pragma unroll 8
            for (int m = 0; m < 128; m++) s = fmaf(e2[m], W[m * 128], s);
            g_cb[l][c] = s;
        }
        cpa_wait0();
    } else {
        cpa_wait0();
    }
    grid_barrier(0, tid);

    // prefetch ew1a (layer 0)
    stage64(b0, ew1 + 0, tid);

    // ================= layers =================
    for (int l = 0; l < L_; l++) {
        float* Pbuf = g_P[l & 1];
        const float* ew1l = ew1 + l * 32768;

        stage64(b1, ew1l + 16384, tid);            // ew1b
        {                                          // sX -> dup'd sATs
            float v = sX[tid];
            sATs[cc * 20 + 2 * rr] = v;
            sATs[cc * 20 + 2 * rr + 1] = v;
        }
        cpa_wait1();        // ew1a (b0) landed
        __syncthreads();

        // ---- proj a: Pi = x @ ew1a + eb1 ----
        {
            u64 acc[4] = {};
            gemm_t(sATs, b0, lane, cg, rg, kq, acc);
            store_part(sPart, acc, lane, cg, rg, kq);
            __syncthreads();                        // b0 free, sPart ready
            stage64(b0, nw1 + l * 32768, tid);      // nw1a -> b0
            sPi[rr * 128 + cc] = reduce8(sPart, tid) + eb1[l * 128 + cc];
            cpa_wait1();    // ew1b (b1) landed
            __syncthreads();
        }
        // ---- proj b: Pj = x @ ew1b -> global ----
        {
            u64 acc[4] = {};
            gemm_t(sATs, b1, lane, cg, rg, kq, acc);
            store_part(sPart, acc, lane, cg, rg, kq);
            __syncthreads();
            Pbuf[(rb * 8 + rr) * 128 + cc] = reduce8(sPart, tid);
            cpa_wait0();    // nw1a (b0) landed
            __syncthreads();
        }
        // ---- proj n: Pn = x @ nw1a + nb1 ----
        {
            u64 acc[4] = {};
            gemm_t(sATs, b0, lane, cg, rg, kq, acc);
            store_part(sPart, acc, lane, cg, rg, kq);
            __syncthreads();
            sPn[rr * 128 + cc] = reduce8(sPart, tid) + nb1[l * 128 + cc];
            __syncthreads();
        }

        grid_barrier(1 + l, tid);   // Pj globally visible

        stage64(b0, Pbuf + b * 32768, tid);            // Pj half0
        stage64(b1, Pbuf + b * 32768 + 16384, tid);    // Pj half1

        // ---- agg (acc persists across halves) ----
        u64 xi[2][2], aacc[2][2] = {};
#pragma unroll
        for (int q = 0; q < 2; q++) {
            ulonglong2 v = *(const ulonglong2*)(sPi + (ig * 2 + q) * 128 + lane * 4);
            xi[q][0] = v.x; xi[q][1] = v.y;
        }
        cpa_wait1();        // Pj half0 landed
        __syncthreads();
        agg_half(b0, sAdj2, xi, aacc, lane, ig, jq);
        __syncthreads();                            // b0 free
        stage64(b0, g_Wc[l], tid);                  // Wc -> b0
        cpa_wait1();        // Pj half1 landed
        __syncthreads();
        agg_half(b1, sAdj2 + 128 * 16, xi, aacc, lane, ig, jq);
        {   // store agg partials (p = jq)
            float* o = sPart + jq * 1024 + ig * 2 * 128 + lane * 4;
#pragma unroll
            for (int q = 0; q < 2; q++) {
                ulonglong2 st; st.x = aacc[q][0]; st.y = aacc[q][1];
                *(ulonglong2*)(o + q * 128) = st;
            }
        }
        __syncthreads();                            // b1 free, sPart ready
        stage64(b1, nw2 + l * 16384, tid);          // nw2 -> b1
        {   // reduce agg -> dup'd sATs
            float v = reduce8(sPart, tid);
            sATs[cc * 20 + 2 * rr] = v;
            sATs[cc * 20 + 2 * rr + 1] = v;
        }
        cpa_wait1();        // Wc (b0) landed
        __syncthreads();

        // ---- nh = relu(Pn + agg@Wc + rs*cb) ----
        {
            u64 acc[4] = {};
            gemm_t(sATs, b0, lane, cg, rg, kq, acc);
            store_part(sPart, acc, lane, cg, rg, kq);
            __syncthreads();                        // b0 free
            float v = reduce8(sPart, tid) + sPn[rr * 128 + cc] + s_rs[rr] * g_cb[l][cc];
            v = fmaxf(v, 0.f);
            sNTs[cc * 20 + 2 * rr] = v;
            sNTs[cc * 20 + 2 * rr + 1] = v;
            __syncthreads();
        }
        stage64(b0, ew1 + (l + 1 < L_ ? l + 1 : 0) * 32768, tid);  // next ew1a
        cpa_wait1();        // nw2 (b1) landed
        __syncthreads();

        // ---- x += nh @ nw2 + nb2 ----
        {
            u64 acc[4] = {};
            gemm_t(sNTs, b1, lane, cg, rg, kq, acc);
            store_part(sPart, acc, lane, cg, rg, kq);
            __syncthreads();
            float v = sX[tid] + reduce8(sPart, tid) + nb2[l * 128 + cc];
            sX[tid] = v;
            if (l == L_ - 1) x[rb * 1024 + tid] = v;
            __syncthreads();
        }
    }
    cpa_wait0();
}

// ---------------- launch ----------------
extern "C" void kernel_launch(void* const* d_in, const int* in_sizes, int n_in,
                              void* d_out, int out_size) {
    const float* nf  = (const float*)d_in[0];
    const float* adj = (const float*)d_in[1];
    const float* ew1 = (const float*)d_in[2];
    const float* eb1 = (const float*)d_in[3];
    const float* ew2 = (const float*)d_in[4];
    const float* eb2 = (const float*)d_in[5];
    const float* nw1 = (const float*)d_in[6];
    const float* nb1 = (const float*)d_in[7];
    const float* nw2 = (const float*)d_in[8];
    const float* nb2 = (const float*)d_in[9];
    float* x = (float*)d_out;

    const int SMEM = SMEM_FLOATS * 4;   // 213024 B
    cudaFuncSetAttribute(k_main, cudaFuncAttributeMaxDynamicSharedMemorySize, SMEM);
    k_main<<<NB, NT, SMEM>>>(x, nf, adj, ew1, eb1, ew2, eb2, nw1, nb1, nw2, nb2);
}

// round 8
// speedup vs baseline: 1.1147x; 1.1147x over previous
#include <cuda_runtime.h>
#include <cstdint>

typedef unsigned long long u64;
#define DEV static __device__ __forceinline__

static constexpr int L_ = 3;
static constexpr int NB = 128;   // 128 CTAs, 8 rows each
static constexpr int NT = 512;   // 16 warps

// ---------------- device globals ----------------
__device__ float g_P[2][1024 * 128];   // double-buffered Pj
__device__ float g_Wc[L_][128 * 128];  // ew2 @ nw1b
__device__ float g_cb[L_][128];        // eb2 @ nw1b
__device__ unsigned g_bar[4];          // monotonic barrier counters (replay-safe)

// ---------------- f32x2 helpers ----------------
DEV u64 pk(float lo, float hi) {
    u64 r; asm("mov.b64 %0,{%1,%2};" : "=l"(r) : "f"(lo), "f"(hi)); return r;
}
DEV void upk(u64 v, float& lo, float& hi) {
    asm("mov.b64 {%0,%1},%2;" : "=f"(lo), "=f"(hi) : "l"(v));
}
DEV u64 add2(u64 a, u64 b) {
    u64 r; asm("add.rn.f32x2 %0,%1,%2;" : "=l"(r) : "l"(a), "l"(b)); return r;
}
DEV u64 fma2(u64 a, u64 b, u64 c) {
    u64 r; asm("fma.rn.f32x2 %0,%1,%2,%3;" : "=l"(r) : "l"(a), "l"(b), "l"(c)); return r;
}
DEV u64 relu2(u64 v) {
    float lo, hi; upk(v, lo, hi);
    return pk(fmaxf(lo, 0.f), fmaxf(hi, 0.f));
}

// ---------------- cp.async helpers ----------------
DEV void cpa16(void* dst, const void* src) {
    unsigned d = (unsigned)__cvta_generic_to_shared(dst);
    asm volatile("cp.async.cg.shared.global [%0],[%1],16;" :: "r"(d), "l"(src) : "memory");
}
DEV void cpa_commit() { asm volatile("cp.async.commit_group;" ::: "memory"); }
DEV void cpa_wait0() { asm volatile("cp.async.wait_group 0;" ::: "memory"); }
DEV void cpa_wait1() { asm volatile("cp.async.wait_group 1;" ::: "memory"); }

// stage 64KB (16384 floats) with 512 threads, one commit group
DEV void stage64(float* dst, const float* src, int tid) {
#pragma unroll
    for (int i = 0; i < 8; i++)
        cpa16(dst + (i * 512 + tid) * 4, src + (i * 512 + tid) * 4);
    cpa_commit();
}

// ---------------- split grid barrier (monotonic counters; replay-safe) ----------------
DEV unsigned ld_acq(const unsigned* p) {
    unsigned v;
    asm volatile("ld.acquire.gpu.global.u32 %0,[%1];" : "=r"(v) : "l"(p) : "memory");
    return v;
}
DEV void bar_arrive(int bidx, int tid, unsigned* sT) {
    __syncthreads();                 // all prior work (incl. global stores) done
    if (tid == 0) {
        __threadfence();             // publish
        unsigned t = atomicAdd(&g_bar[bidx], 1u);
        *sT = (t / (unsigned)NB + 1u) * (unsigned)NB;
    }
}
DEV void bar_wait(int bidx, int tid, unsigned* sT) {
    __syncthreads();                 // sT visible; interim work done
    if (tid == 0) {
        unsigned target = *sT;
        while (ld_acq(&g_bar[bidx]) < target) { __nanosleep(64); }
        __threadfence();
    }
    __syncthreads();
}

// ---------------- r=4 k-split-8 GEMM (W in smem) ----------------
// warp = (rg = w&1 rowgroup of 4, kq = w>>1 of 8, 16 k each), lane = 4 cols.
// dup'd A layout: ATs[k*20 + 2r] = ATs[k*20+2r+1] = A[r][k]
DEV void gemm_r4k8(const float* __restrict__ ATs, const float* __restrict__ Wsm,
                   int lane, int rg, int kq, u64 acc[4][2]) {
    const float* ap = ATs + kq * 16 * 20 + rg * 8;
    const float* wp = Wsm + kq * 16 * 128 + lane * 4;
#pragma unroll 8
    for (int k = 0; k < 16; k++) {
        ulonglong2 a01 = *(const ulonglong2*)(ap + k * 20);
        ulonglong2 a23 = *(const ulonglong2*)(ap + k * 20 + 4);
        ulonglong2 wv = *(const ulonglong2*)(wp + k * 128);
        acc[0][0] = fma2(a01.x, wv.x, acc[0][0]);
        acc[0][1] = fma2(a01.x, wv.y, acc[0][1]);
        acc[1][0] = fma2(a01.y, wv.x, acc[1][0]);
        acc[1][1] = fma2(a01.y, wv.y, acc[1][1]);
        acc[2][0] = fma2(a23.x, wv.x, acc[2][0]);
        acc[2][1] = fma2(a23.x, wv.y, acc[2][1]);
        acc[3][0] = fma2(a23.y, wv.x, acc[3][0]);
        acc[3][1] = fma2(a23.y, wv.y, acc[3][1]);
    }
}

DEV void store_part8(float* sPart, const u64 acc[4][2], int lane, int rg, int kq) {
    float* o = sPart + kq * 1024 + rg * 4 * 128 + lane * 4;
#pragma unroll
    for (int r = 0; r < 4; r++) {
        float v0, v1, v2, v3;
        upk(acc[r][0], v0, v1); upk(acc[r][1], v2, v3);
        *(float4*)(o + r * 128) = make_float4(v0, v1, v2, v3);
    }
}

DEV float reduce8(const float* __restrict__ sPart, int idx) {
    float v = 0.f;
#pragma unroll
    for (int p = 0; p < 8; p++) v += sPart[p * 1024 + idx];
    return v;
}

// ---------------- agg half: warp=(ig2,jq8), thread = 4 i x 4 d, 16 j ----------------
DEV void agg_half(const float* __restrict__ Pjh, const float* __restrict__ adjh,
                  const u64 xi[4][2], u64 acc[4][2], int lane, int ig, int jq) {
    const float* pj = Pjh + jq * 16 * 128 + lane * 4;
    const float* ad = adjh + jq * 16 * 16 + ig * 8;
#pragma unroll 4
    for (int jj = 0; jj < 16; jj++) {
        ulonglong2 xj = *(const ulonglong2*)(pj + jj * 128);
        ulonglong2 a01 = *(const ulonglong2*)(ad + jj * 16);
        ulonglong2 a23 = *(const ulonglong2*)(ad + jj * 16 + 4);
        u64 t;
        t = relu2(add2(xi[0][0], xj.x)); acc[0][0] = fma2(t, a01.x, acc[0][0]);
        t = relu2(add2(xi[0][1], xj.y)); acc[0][1] = fma2(t, a01.x, acc[0][1]);
        t = relu2(add2(xi[1][0], xj.x)); acc[1][0] = fma2(t, a01.y, acc[1][0]);
        t = relu2(add2(xi[1][1], xj.y)); acc[1][1] = fma2(t, a01.y, acc[1][1]);
        t = relu2(add2(xi[2][0], xj.x)); acc[2][0] = fma2(t, a23.x, acc[2][0]);
        t = relu2(add2(xi[2][1], xj.y)); acc[2][1] = fma2(t, a23.x, acc[2][1]);
        t = relu2(add2(xi[3][0], xj.x)); acc[3][0] = fma2(t, a23.y, acc[3][0]);
        t = relu2(add2(xi[3][1], xj.y)); acc[3][1] = fma2(t, a23.y, acc[3][1]);
    }
}

// ---------------- smem layout (floats) ----------------
// b0 0 (16384) | b1 16384 (16384) | sPart 32768 (8192) | sATs 40960 (2560)
// sNTs 43520 (2560) | sPi 46080 (1024) | sPn 47104 (1024) | sAdj2 48128 (4096)
// s_rs 52224 (8) | sX 52232 (1024) | sBarT 53256 (1 uint)
static constexpr int SMEM_FLOATS = 53260;   // 213040 B

__global__ void __launch_bounds__(NT, 1) k_main(
    float* __restrict__ x, const float* __restrict__ nf, const float* __restrict__ adj,
    const float* __restrict__ ew1, const float* __restrict__ eb1,
    const float* __restrict__ ew2, const float* __restrict__ eb2,
    const float* __restrict__ nw1, const float* __restrict__ nb1,
    const float* __restrict__ nw2, const float* __restrict__ nb2) {
    extern __shared__ float sm[];
    float* b0 = sm;
    float* b1 = sm + 16384;
    float* sPart = sm + 32768;
    float* sATs = sm + 40960;
    float* sNTs = sm + 43520;
    float* sPi = sm + 46080;
    float* sPn = sm + 47104;
    float* sAdj2 = sm + 48128;
    float* s_rs = sm + 52224;
    float* sX = sm + 52232;
    unsigned* sBarT = (unsigned*)(sm + 53256);

    int tid = threadIdx.x, lane = tid & 31, w = tid >> 5;
    int rb = blockIdx.x;        // rows rb*8 .. rb*8+7
    int b = rb >> 5;            // batch
    int il0 = (rb & 31) * 8;    // local i base in batch
    int rg = w & 1, kq = w >> 1;   // gemm warp roles
    int ig = w & 1, jq = w >> 1;   // agg warp roles
    int rr = tid >> 7, cc = tid & 127;   // reduce/epilogue roles (q adds 4 to rr)

    // ================= setup: produce Wc/cb, arrive, local setup, wait ==========
    if (rb < 48) {   // Wc[l] = ew2[l] @ nw1b[l]
        int l = rb / 16, r8 = rb % 16;
        stage64(b0, nw1 + l * 32768 + 16384, tid);
#pragma unroll
        for (int q = 0; q < 2; q++) {
            int idx = q * 512 + tid;
            int r = idx >> 7, k = idx & 127;
            float v = ew2[l * 16384 + (r8 * 8 + r) * 128 + k];
            sATs[k * 20 + 2 * r] = v;
            sATs[k * 20 + 2 * r + 1] = v;
        }
        cpa_wait0();
        __syncthreads();
        u64 acc[4][2] = {};
        gemm_r4k8(sATs, b0, lane, rg, kq, acc);
        store_part8(sPart, acc, lane, rg, kq);
        __syncthreads();
#pragma unroll
        for (int q = 0; q < 2; q++) {
            int idx = q * 512 + tid;
            g_Wc[l][(r8 * 8 + rr + q * 4) * 128 + cc] = reduce8(sPart, idx);
        }
    } else if (rb == 48) {
        if (tid < 384) {
            int l = tid >> 7, c = tid & 127;
            const float* e2 = eb2 + l * 128;
            const float* W = nw1 + l * 32768 + 16384 + c;
            float s = 0.f;
#pragma unroll 8
            for (int m = 0; m < 128; m++) s = fmaf(e2[m], W[m * 128], s);
            g_cb[l][c] = s;
        }
    }
    bar_arrive(0, tid, sBarT);

    // ---- CTA-local setup, overlapped with other CTAs' Wc work ----
#pragma unroll
    for (int q = 0; q < 2; q++) sX[q * 512 + tid] = nf[rb * 1024 + q * 512 + tid];
    const float* adjb = adj + (size_t)(b * 256 + il0) * 256;
#pragma unroll
    for (int e = 0; e < 4; e++) {
        int idx = e * 512 + tid;
        int r = idx >> 8, j = idx & 255;
        float v = adjb[r * 256 + j];
        sAdj2[j * 16 + 2 * r] = v;
        sAdj2[j * 16 + 2 * r + 1] = v;
    }
    if (w < 8) {
        float s = 0.f;
        const float* row = adjb + w * 256;
#pragma unroll
        for (int j = lane; j < 256; j += 32) s += row[j];
#pragma unroll
        for (int o = 16; o; o >>= 1) s += __shfl_xor_sync(~0u, s, o);
        if (!lane) s_rs[w] = s;
    }
    stage64(b0, ew1 + 16384, tid);   // ew1b layer 0   [1 pending]
    bar_wait(0, tid, sBarT);

    // ================= layers =================
    for (int l = 0; l < L_; l++) {
        float* Pbuf = g_P[l & 1];
        const float* ew1l = ew1 + l * 32768;

        stage64(b1, ew1l, tid);                    // ew1a    [2 pending]
#pragma unroll
        for (int q = 0; q < 2; q++) {              // sX -> dup'd sATs
            int idx = q * 512 + tid;
            int r = idx >> 7, k = idx & 127;
            float v = sX[idx];
            sATs[k * 20 + 2 * r] = v;
            sATs[k * 20 + 2 * r + 1] = v;
        }
        cpa_wait1();        // ew1b (b0) landed
        __syncthreads();

        // ---- Pj = x @ ew1b -> global, then ARRIVE ----
        {
            u64 acc[4][2] = {};
            gemm_r4k8(sATs, b0, lane, rg, kq, acc);
            store_part8(sPart, acc, lane, rg, kq);
            __syncthreads();
#pragma unroll
            for (int q = 0; q < 2; q++) {
                int idx = q * 512 + tid;
                Pbuf[(rb * 8 + rr + q * 4) * 128 + cc] = reduce8(sPart, idx);
            }
        }
        bar_arrive(1 + l, tid, sBarT);             // Pj published; b0 free

        stage64(b0, nw1 + l * 32768, tid);         // nw1a    [2 pending]
        cpa_wait1();        // ew1a (b1) landed
        __syncthreads();

        // ---- Pi = x @ ew1a + eb1 (hidden behind barrier) ----
        {
            u64 acc[4][2] = {};
            gemm_r4k8(sATs, b1, lane, rg, kq, acc);
            store_part8(sPart, acc, lane, rg, kq);
            __syncthreads();
            float bv = eb1[l * 128 + cc];
#pragma unroll
            for (int q = 0; q < 2; q++) {
                int idx = q * 512 + tid;
                sPi[(rr + q * 4) * 128 + cc] = reduce8(sPart, idx) + bv;
            }
            cpa_wait0();    // nw1a (b0) landed
            __syncthreads();
        }
        // ---- Pn = x @ nw1a + nb1 (hidden behind barrier) ----
        {
            u64 acc[4][2] = {};
            gemm_r4k8(sATs, b0, lane, rg, kq, acc);
            store_part8(sPart, acc, lane, rg, kq);
            __syncthreads();
            float bv = nb1[l * 128 + cc];
#pragma unroll
            for (int q = 0; q < 2; q++) {
                int idx = q * 512 + tid;
                sPn[(rr + q * 4) * 128 + cc] = reduce8(sPart, idx) + bv;
            }
        }
        bar_wait(1 + l, tid, sBarT);   // all Pj visible; b0 free

        stage64(b0, Pbuf + b * 32768, tid);            // Pj half0  [1]
        stage64(b1, Pbuf + b * 32768 + 16384, tid);    // Pj half1  [2]

        // ---- agg (acc persists across halves) ----
        u64 xi[4][2], aacc[4][2] = {};
#pragma unroll
        for (int q = 0; q < 4; q++) {
            ulonglong2 v = *(const ulonglong2*)(sPi + (ig * 4 + q) * 128 + lane * 4);
            xi[q][0] = v.x; xi[q][1] = v.y;
        }
        cpa_wait1();        // Pj half0 landed
        __syncthreads();
        agg_half(b0, sAdj2, xi, aacc, lane, ig, jq);
        __syncthreads();                            // b0 free
        stage64(b0, g_Wc[l], tid);                  // Wc -> b0  [2]
        cpa_wait1();        // Pj half1 landed
        __syncthreads();
        agg_half(b1, sAdj2 + 128 * 16, xi, aacc, lane, ig, jq);
        {   // store agg partials (p = jq)
            float* o = sPart + jq * 1024 + ig * 4 * 128 + lane * 4;
#pragma unroll
            for (int q = 0; q < 4; q++) {
                float v0, v1, v2, v3;
                upk(aacc[q][0], v0, v1); upk(aacc[q][1], v2, v3);
                *(float4*)(o + q * 128) = make_float4(v0, v1, v2, v3);
            }
        }
        __syncthreads();                            // b1 free, sPart ready
        stage64(b1, nw2 + l * 16384, tid);          // nw2 -> b1  [2]
#pragma unroll
        for (int q = 0; q < 2; q++) {               // reduce agg -> dup'd sATs
            int idx = q * 512 + tid;
            float v = reduce8(sPart, idx);
            sATs[cc * 20 + 2 * (rr + q * 4)] = v;
            sATs[cc * 20 + 2 * (rr + q * 4) + 1] = v;
        }
        cpa_wait1();        // Wc (b0) landed
        __syncthreads();

        // ---- nh = relu(Pn + agg@Wc + rs*cb) ----
        {
            u64 acc[4][2] = {};
            gemm_r4k8(sATs, b0, lane, rg, kq, acc);
            store_part8(sPart, acc, lane, rg, kq);
            __syncthreads();                        // b0 free
            float cbv = g_cb[l][cc];
#pragma unroll
            for (int q = 0; q < 2; q++) {
                int idx = q * 512 + tid;
                int r = rr + q * 4;
                float v = reduce8(sPart, idx) + sPn[r * 128 + cc] + s_rs[r] * cbv;
                v = fmaxf(v, 0.f);
                sNTs[cc * 20 + 2 * r] = v;
                sNTs[cc * 20 + 2 * r + 1] = v;
            }
            __syncthreads();
        }
        stage64(b0, ew1 + (l + 1 < L_ ? l + 1 : 0) * 32768 + 16384, tid);  // next ew1b [2]
        cpa_wait1();        // nw2 (b1) landed
        __syncthreads();

        // ---- x += nh @ nw2 + nb2 ----
        {
            u64 acc[4][2] = {};
            gemm_r4k8(sNTs, b1, lane, rg, kq, acc);
            store_part8(sPart, acc, lane, rg, kq);
            __syncthreads();
            float bv = nb2[l * 128 + cc];
#pragma unroll
            for (int q = 0; q < 2; q++) {
                int idx = q * 512 + tid;
                float v = sX[idx] + reduce8(sPart, idx) + bv;
                sX[idx] = v;
                if (l == L_ - 1) x[rb * 1024 + idx] = v;
            }
            __syncthreads();
        }
    }
    cpa_wait0();
}

// ---------------- launch ----------------
extern "C" void kernel_launch(void* const* d_in, const int* in_sizes, int n_in,
                              void* d_out, int out_size) {
    const float* nf  = (const float*)d_in[0];
    const float* adj = (const float*)d_in[1];
    const float* ew1 = (const float*)d_in[2];
    const float* eb1 = (const float*)d_in[3];
    const float* ew2 = (const float*)d_in[4];
    const float* eb2 = (const float*)d_in[5];
    const float* nw1 = (const float*)d_in[6];
    const float* nb1 = (const float*)d_in[7];
    const float* nw2 = (const float*)d_in[8];
    const float* nb2 = (const float*)d_in[9];
    float* x = (float*)d_out;

    const int SMEM = SMEM_FLOATS * 4;   // 213040 B
    cudaFuncSetAttribute(k_main, cudaFuncAttributeMaxDynamicSharedMemorySize, SMEM);
    k_main<<<NB, NT, SMEM>>>(x, nf, adj, ew1, eb1, ew2, eb2, nw1, nb1, nw2, nb2);
}

// round 9
// speedup vs baseline: 1.1410x; 1.0236x over previous
#include <cuda_runtime.h>
#include <cstdint>

typedef unsigned long long u64;
#define DEV static __device__ __forceinline__

static constexpr int L_ = 3;
static constexpr int NB = 128;   // 128 CTAs, 8 rows each
static constexpr int NT = 512;   // 16 warps

// ---------------- device globals ----------------
__device__ float g_P[2][1024 * 128];   // double-buffered Pj
__device__ float g_Wc[L_][128 * 128];  // ew2 @ nw1b
__device__ float g_cb[L_][128];        // eb2 @ nw1b
__device__ unsigned g_bar[4];          // monotonic barrier counters (replay-safe)

// ---------------- f32x2 helpers ----------------
DEV u64 pk(float lo, float hi) {
    u64 r; asm("mov.b64 %0,{%1,%2};" : "=l"(r) : "f"(lo), "f"(hi)); return r;
}
DEV void upk(u64 v, float& lo, float& hi) {
    asm("mov.b64 {%0,%1},%2;" : "=f"(lo), "=f"(hi) : "l"(v));
}
DEV u64 add2(u64 a, u64 b) {
    u64 r; asm("add.rn.f32x2 %0,%1,%2;" : "=l"(r) : "l"(a), "l"(b)); return r;
}
DEV u64 fma2(u64 a, u64 b, u64 c) {
    u64 r; asm("fma.rn.f32x2 %0,%1,%2,%3;" : "=l"(r) : "l"(a), "l"(b), "l"(c)); return r;
}
DEV u64 relu2(u64 v) {
    float lo, hi; upk(v, lo, hi);
    return pk(fmaxf(lo, 0.f), fmaxf(hi, 0.f));
}

// ---------------- cp.async helpers ----------------
DEV void cpa16(void* dst, const void* src) {
    unsigned d = (unsigned)__cvta_generic_to_shared(dst);
    asm volatile("cp.async.cg.shared.global [%0],[%1],16;" :: "r"(d), "l"(src) : "memory");
}
DEV void cpa_commit() { asm volatile("cp.async.commit_group;" ::: "memory"); }
DEV void cpa_wait0() { asm volatile("cp.async.wait_group 0;" ::: "memory"); }
DEV void cpa_wait1() { asm volatile("cp.async.wait_group 1;" ::: "memory"); }

// stage 64KB (16384 floats) with 512 threads, one commit group
DEV void stage64(float* dst, const float* src, int tid) {
#pragma unroll
    for (int i = 0; i < 8; i++)
        cpa16(dst + (i * 512 + tid) * 4, src + (i * 512 + tid) * 4);
    cpa_commit();
}

// ---------------- split grid barrier (monotonic counters; replay-safe) ----------------
DEV unsigned ld_acq(const unsigned* p) {
    unsigned v;
    asm volatile("ld.acquire.gpu.global.u32 %0,[%1];" : "=r"(v) : "l"(p) : "memory");
    return v;
}
DEV void bar_arrive(int bidx, int tid, unsigned* sT) {
    __syncthreads();
    if (tid == 0) {
        __threadfence();
        unsigned t = atomicAdd(&g_bar[bidx], 1u);
        *sT = (t / (unsigned)NB + 1u) * (unsigned)NB;
    }
}
DEV void bar_wait(int bidx, int tid, unsigned* sT) {
    __syncthreads();
    if (tid == 0) {
        unsigned target = *sT;
        while (ld_acq(&g_bar[bidx]) < target) { __nanosleep(64); }
        __threadfence();
    }
    __syncthreads();
}

// ---------------- r=4 k-split-8 GEMM (W in smem) ----------------
// warp = (rg = w&1, kq = w>>1 of 8, 16 k each), lane = 4 cols.
// dup'd A layout: ATs[k*20 + 2r] = ATs[k*20+2r+1] = A[r][k]
DEV void gemm_r4k8(const float* __restrict__ ATs, const float* __restrict__ Wsm,
                   int lane, int rg, int kq, u64 acc[4][2]) {
    const float* ap = ATs + kq * 16 * 20 + rg * 8;
    const float* wp = Wsm + kq * 16 * 128 + lane * 4;
#pragma unroll
    for (int k = 0; k < 16; k++) {
        ulonglong2 a01 = *(const ulonglong2*)(ap + k * 20);
        ulonglong2 a23 = *(const ulonglong2*)(ap + k * 20 + 4);
        ulonglong2 wv = *(const ulonglong2*)(wp + k * 128);
        acc[0][0] = fma2(a01.x, wv.x, acc[0][0]);
        acc[0][1] = fma2(a01.x, wv.y, acc[0][1]);
        acc[1][0] = fma2(a01.y, wv.x, acc[1][0]);
        acc[1][1] = fma2(a01.y, wv.y, acc[1][1]);
        acc[2][0] = fma2(a23.x, wv.x, acc[2][0]);
        acc[2][1] = fma2(a23.x, wv.y, acc[2][1]);
        acc[3][0] = fma2(a23.y, wv.x, acc[3][0]);
        acc[3][1] = fma2(a23.y, wv.y, acc[3][1]);
    }
}

// ---------------- merged 8x256 GEMM: warp=(cg2,rg2,kq4), 32 k each ----------------
DEV void gemm_m(const float* __restrict__ ATs, const float* __restrict__ Wsm,
                int lane, int rg, int kq, u64 acc[4][2]) {
    const float* ap = ATs + kq * 32 * 20 + rg * 8;
    const float* wp = Wsm + kq * 32 * 128 + lane * 4;
#pragma unroll 16
    for (int k = 0; k < 32; k++) {
        ulonglong2 a01 = *(const ulonglong2*)(ap + k * 20);
        ulonglong2 a23 = *(const ulonglong2*)(ap + k * 20 + 4);
        ulonglong2 wv = *(const ulonglong2*)(wp + k * 128);
        acc[0][0] = fma2(a01.x, wv.x, acc[0][0]);
        acc[0][1] = fma2(a01.x, wv.y, acc[0][1]);
        acc[1][0] = fma2(a01.y, wv.x, acc[1][0]);
        acc[1][1] = fma2(a01.y, wv.y, acc[1][1]);
        acc[2][0] = fma2(a23.x, wv.x, acc[2][0]);
        acc[2][1] = fma2(a23.x, wv.y, acc[2][1]);
        acc[3][0] = fma2(a23.y, wv.x, acc[3][0]);
        acc[3][1] = fma2(a23.y, wv.y, acc[3][1]);
    }
}

DEV void store_part8(float* sPart, const u64 acc[4][2], int lane, int rg, int kq) {
    float* o = sPart + kq * 1024 + rg * 4 * 128 + lane * 4;
#pragma unroll
    for (int r = 0; r < 4; r++) {
        float v0, v1, v2, v3;
        upk(acc[r][0], v0, v1); upk(acc[r][1], v2, v3);
        *(float4*)(o + r * 128) = make_float4(v0, v1, v2, v3);
    }
}

DEV float reduce8(const float* __restrict__ sPart, int idx) {
    float v = 0.f;
#pragma unroll
    for (int p = 0; p < 8; p++) v += sPart[p * 1024 + idx];
    return v;
}

// ---------------- agg half: warp=(ig2,jq8), thread = 4 i x 4 d, 16 j ----------------
DEV void agg_half(const float* __restrict__ Pjh, const float* __restrict__ adjh,
                  const u64 xi[4][2], u64 acc[4][2], int lane, int ig, int jq) {
    const float* pj = Pjh + jq * 16 * 128 + lane * 4;
    const float* ad = adjh + jq * 16 * 16 + ig * 8;
#pragma unroll 16
    for (int jj = 0; jj < 16; jj++) {
        ulonglong2 xj = *(const ulonglong2*)(pj + jj * 128);
        ulonglong2 a01 = *(const ulonglong2*)(ad + jj * 16);
        ulonglong2 a23 = *(const ulonglong2*)(ad + jj * 16 + 4);
        u64 t;
        t = relu2(add2(xi[0][0], xj.x)); acc[0][0] = fma2(t, a01.x, acc[0][0]);
        t = relu2(add2(xi[0][1], xj.y)); acc[0][1] = fma2(t, a01.x, acc[0][1]);
        t = relu2(add2(xi[1][0], xj.x)); acc[1][0] = fma2(t, a01.y, acc[1][0]);
        t = relu2(add2(xi[1][1], xj.y)); acc[1][1] = fma2(t, a01.y, acc[1][1]);
        t = relu2(add2(xi[2][0], xj.x)); acc[2][0] = fma2(t, a23.x, acc[2][0]);
        t = relu2(add2(xi[2][1], xj.y)); acc[2][1] = fma2(t, a23.x, acc[2][1]);
        t = relu2(add2(xi[3][0], xj.x)); acc[3][0] = fma2(t, a23.y, acc[3][0]);
        t = relu2(add2(xi[3][1], xj.y)); acc[3][1] = fma2(t, a23.y, acc[3][1]);
    }
}

// ---------------- smem layout (floats) ----------------
// b0 0 (16384) | b1 16384 (16384) | sPart 32768 (8192) | sATs 40960 (2560)
// sNTs 43520 (2560) | sPi 46080 (1024) | sPn 47104 (1024) | sAdj2 48128 (4096)
// s_rs 52224 (8) | sX 52232 (1024) | sBarT 53256 (1 uint)
static constexpr int SMEM_FLOATS = 53260;   // 213040 B

__global__ void __launch_bounds__(NT, 1) k_main(
    float* __restrict__ x, const float* __restrict__ nf, const float* __restrict__ adj,
    const float* __restrict__ ew1, const float* __restrict__ eb1,
    const float* __restrict__ ew2, const float* __restrict__ eb2,
    const float* __restrict__ nw1, const float* __restrict__ nb1,
    const float* __restrict__ nw2, const float* __restrict__ nb2) {
    extern __shared__ float sm[];
    float* b0 = sm;
    float* b1 = sm + 16384;
    float* sPart = sm + 32768;
    float* sATs = sm + 40960;
    float* sNTs = sm + 43520;
    float* sPi = sm + 46080;
    float* sPn = sm + 47104;
    float* sAdj2 = sm + 48128;
    float* s_rs = sm + 52224;
    float* sX = sm + 52232;
    unsigned* sBarT = (unsigned*)(sm + 53256);

    int tid = threadIdx.x, lane = tid & 31, w = tid >> 5;
    int rb = blockIdx.x;        // rows rb*8 .. rb*8+7
    int b = rb >> 5;            // batch
    int il0 = (rb & 31) * 8;    // local i base in batch
    int rg = w & 1, kq = w >> 1;              // r4k8 roles
    int mcg = w & 1, mrg = (w >> 1) & 1, mkq = w >> 2;   // merged-GEMM roles
    int ig = w & 1, jq = w >> 1;              // agg roles
    int rr = tid >> 7, cc = tid & 127;        // reduce/epilogue roles

    // ================= setup: produce Wc/cb, arrive, local setup, wait ==========
    if (rb < 48) {   // Wc[l] = ew2[l] @ nw1b[l]
        int l = rb / 16, r8 = rb % 16;
        stage64(b0, nw1 + l * 32768 + 16384, tid);
#pragma unroll
        for (int q = 0; q < 2; q++) {
            int idx = q * 512 + tid;
            int r = idx >> 7, k = idx & 127;
            float v = ew2[l * 16384 + (r8 * 8 + r) * 128 + k];
            *(float2*)(sATs + k * 20 + 2 * r) = make_float2(v, v);
        }
        cpa_wait0();
        __syncthreads();
        u64 acc[4][2] = {};
        gemm_r4k8(sATs, b0, lane, rg, kq, acc);
        store_part8(sPart, acc, lane, rg, kq);
        __syncthreads();
#pragma unroll
        for (int q = 0; q < 2; q++) {
            int idx = q * 512 + tid;
            g_Wc[l][(r8 * 8 + rr + q * 4) * 128 + cc] = reduce8(sPart, idx);
        }
    } else if (rb == 48) {
        if (tid < 384) {
            int l = tid >> 7, c = tid & 127;
            const float* e2 = eb2 + l * 128;
            const float* W = nw1 + l * 32768 + 16384 + c;
            float s = 0.f;
#pragma unroll 8
            for (int m = 0; m < 128; m++) s = fmaf(e2[m], W[m * 128], s);
            g_cb[l][c] = s;
        }
    }
    bar_arrive(0, tid, sBarT);

    // ---- CTA-local setup, overlapped with other CTAs' Wc work ----
#pragma unroll
    for (int q = 0; q < 2; q++) sX[q * 512 + tid] = nf[rb * 1024 + q * 512 + tid];
    const float* adjb = adj + (size_t)(b * 256 + il0) * 256;
#pragma unroll
    for (int e = 0; e < 4; e++) {
        int idx = e * 512 + tid;
        int r = idx >> 8, j = idx & 255;
        float v = adjb[r * 256 + j];
        *(float2*)(sAdj2 + j * 16 + 2 * r) = make_float2(v, v);
    }
    if (w < 8) {
        float s = 0.f;
        const float* row = adjb + w * 256;
#pragma unroll
        for (int j = lane; j < 256; j += 32) s += row[j];
#pragma unroll
        for (int o = 16; o; o >>= 1) s += __shfl_xor_sync(~0u, s, o);
        if (!lane) s_rs[w] = s;
    }
    stage64(b0, ew1 + 16384, tid);   // ew1b layer 0   [1 pending]
    bar_wait(0, tid, sBarT);

    // ================= layers =================
    for (int l = 0; l < L_; l++) {
        float* Pbuf = g_P[l & 1];
        const float* ew1l = ew1 + l * 32768;

        stage64(b1, ew1l, tid);                    // ew1a    [2 pending]
#pragma unroll
        for (int q = 0; q < 2; q++) {              // sX -> dup'd sATs
            int idx = q * 512 + tid;
            int r = idx >> 7, k = idx & 127;
            float v = sX[idx];
            *(float2*)(sATs + k * 20 + 2 * r) = make_float2(v, v);
        }
        cpa_wait1();        // ew1b (b0) landed
        __syncthreads();

        // ---- Pj = x @ ew1b -> global, then ARRIVE ----
        {
            u64 acc[4][2] = {};
            gemm_r4k8(sATs, b0, lane, rg, kq, acc);
            store_part8(sPart, acc, lane, rg, kq);
            __syncthreads();                       // b0 reads done
            stage64(b0, nw1 + l * 32768, tid);     // nw1a -> b0  [2: ew1a, nw1a]
#pragma unroll
            for (int q = 0; q < 2; q++) {
                int idx = q * 512 + tid;
                Pbuf[(rb * 8 + rr + q * 4) * 128 + cc] = reduce8(sPart, idx);
            }
        }
        bar_arrive(1 + l, tid, sBarT);             // Pj published

        cpa_wait0();        // ew1a (b1) + nw1a (b0) landed
        __syncthreads();

        // ---- merged: [Pi|Pn] = x @ [ew1a | nw1a] + [eb1|nb1] (hidden behind barrier) ----
        {
            u64 acc[4][2] = {};
            gemm_m(sATs, mcg ? b0 : b1, lane, mrg, mkq, acc);
            {   // store to sPart[kq][8r][256c]
                float* o = sPart + mkq * 2048 + mrg * 4 * 256 + mcg * 128 + lane * 4;
#pragma unroll
                for (int r = 0; r < 4; r++) {
                    float v0, v1, v2, v3;
                    upk(acc[r][0], v0, v1); upk(acc[r][1], v2, v3);
                    *(float4*)(o + r * 256) = make_float4(v0, v1, v2, v3);
                }
            }
            __syncthreads();
#pragma unroll
            for (int q = 0; q < 4; q++) {
                int idx = q * 512 + tid;
                int r = idx >> 8, c = idx & 255;
                float v = 0.f;
#pragma unroll
                for (int p = 0; p < 4; p++) v += sPart[p * 2048 + idx];
                if (c < 128) sPi[r * 128 + c] = v + eb1[l * 128 + c];
                else         sPn[r * 128 + c - 128] = v + nb1[l * 128 + (c - 128)];
            }
        }
        bar_wait(1 + l, tid, sBarT);   // all Pj visible; b0,b1 free

        stage64(b0, Pbuf + b * 32768, tid);            // Pj half0  [1]
        stage64(b1, Pbuf + b * 32768 + 16384, tid);    // Pj half1  [2]

        // ---- agg (acc persists across halves) ----
        u64 xi[4][2], aacc[4][2] = {};
#pragma unroll
        for (int q = 0; q < 4; q++) {
            ulonglong2 v = *(const ulonglong2*)(sPi + (ig * 4 + q) * 128 + lane * 4);
            xi[q][0] = v.x; xi[q][1] = v.y;
        }
        cpa_wait1();        // Pj half0 landed
        __syncthreads();
        agg_half(b0, sAdj2, xi, aacc, lane, ig, jq);
        __syncthreads();                            // b0 free
        stage64(b0, g_Wc[l], tid);                  // Wc -> b0  [2]
        cpa_wait1();        // Pj half1 landed
        __syncthreads();
        agg_half(b1, sAdj2 + 128 * 16, xi, aacc, lane, ig, jq);
        {   // store agg partials (p = jq)
            float* o = sPart + jq * 1024 + ig * 4 * 128 + lane * 4;
#pragma unroll
            for (int q = 0; q < 4; q++) {
                float v0, v1, v2, v3;
                upk(aacc[q][0], v0, v1); upk(aacc[q][1], v2, v3);
                *(float4*)(o + q * 128) = make_float4(v0, v1, v2, v3);
            }
        }
        __syncthreads();                            // b1 free, sPart ready
        stage64(b1, nw2 + l * 16384, tid);          // nw2 -> b1  [2]
#pragma unroll
        for (int q = 0; q < 2; q++) {               // reduce agg -> dup'd sATs
            int idx = q * 512 + tid;
            float v = reduce8(sPart, idx);
            *(float2*)(sATs + cc * 20 + 2 * (rr + q * 4)) = make_float2(v, v);
        }
        cpa_wait1();        // Wc (b0) landed
        __syncthreads();

        // ---- nh = relu(Pn + agg@Wc + rs*cb) ----
        {
            u64 acc[4][2] = {};
            gemm_r4k8(sATs, b0, lane, rg, kq, acc);
            store_part8(sPart, acc, lane, rg, kq);
            __syncthreads();                        // b0 free
            float cbv = g_cb[l][cc];
#pragma unroll
            for (int q = 0; q < 2; q++) {
                int idx = q * 512 + tid;
                int r = rr + q * 4;
                float v = reduce8(sPart, idx) + sPn[r * 128 + cc] + s_rs[r] * cbv;
                v = fmaxf(v, 0.f);
                *(float2*)(sNTs + cc * 20 + 2 * r) = make_float2(v, v);
            }
            __syncthreads();
        }
        stage64(b0, ew1 + (l + 1 < L_ ? l + 1 : 0) * 32768 + 16384, tid);  // next ew1b [2]
        cpa_wait1();        // nw2 (b1) landed
        __syncthreads();

        // ---- x += nh @ nw2 + nb2 ----
        {
            u64 acc[4][2] = {};
            gemm_r4k8(sNTs, b1, lane, rg, kq, acc);
            store_part8(sPart, acc, lane, rg, kq);
            __syncthreads();
            float bv = nb2[l * 128 + cc];
#pragma unroll
            for (int q = 0; q < 2; q++) {
                int idx = q * 512 + tid;
                float v = sX[idx] + reduce8(sPart, idx) + bv;
                sX[idx] = v;
                if (l == L_ - 1) x[rb * 1024 + idx] = v;
            }
            __syncthreads();
        }
    }
    cpa_wait0();
}

// ---------------- launch ----------------
extern "C" void kernel_launch(void* const* d_in, const int* in_sizes, int n_in,
                              void* d_out, int out_size) {
    const float* nf  = (const float*)d_in[0];
    const float* adj = (const float*)d_in[1];
    const float* ew1 = (const float*)d_in[2];
    const float* eb1 = (const float*)d_in[3];
    const float* ew2 = (const float*)d_in[4];
    const float* eb2 = (const float*)d_in[5];
    const float* nw1 = (const float*)d_in[6];
    const float* nb1 = (const float*)d_in[7];
    const float* nw2 = (const float*)d_in[8];
    const float* nb2 = (const float*)d_in[9];
    float* x = (float*)d_out;

    const int SMEM = SMEM_FLOATS * 4;   // 213040 B
    cudaFuncSetAttribute(k_main, cudaFuncAttributeMaxDynamicSharedMemorySize, SMEM);
    k_main<<<NB, NT, SMEM>>>(x, nf, adj, ew1, eb1, ew2, eb2, nw1, nb1, nw2, nb2);
}